// round 14
// baseline (speedup 1.0000x reference)
#include <cuda_runtime.h>
#include <cuda_bf16.h>
#include <cstdint>

#define BATCH   512
#define NACT    256
#define ENT_D   256
#define REL_D   256
#define HIST_D  512
#define ACT_DIM 512
#define IN_DIM  1024
#define HUGE_F  1e31f
#define EPS_F   1e-20f

// Scratch (referenced only inside device code)
__device__ float g_H [BATCH * ACT_DIM];
__device__ float g_X2[BATCH * ACT_DIM];

__device__ __forceinline__ float to_tf32(float x) {
    uint32_t u;
    asm("cvt.rna.tf32.f32 %0, %1;" : "=r"(u) : "f"(x));
    return __uint_as_float(u);
}

// ---------------------------------------------------------------------------
// GEMM: C = act(A @ W + bias), tf32 mma, double-buffered register prefetch.
// 256 thr (8 warps), block tile 32x64, warp tile 16x16, BK=64, grid 8x16.
// FIRST: A row = virtual concat [ent_emb[cur]|hist|rel_emb[qr]] (K=1024).
// ---------------------------------------------------------------------------
template <int K, bool FIRST>
__global__ void mma_gemm_kernel(const float* __restrict__ W,
                                const float* __restrict__ bias,
                                const int* __restrict__ cur,
                                const int* __restrict__ qr,
                                const float* __restrict__ hist,
                                const float* __restrict__ ent_emb,
                                const float* __restrict__ rel_emb) {
    float* C = FIRST ? (float*)g_H : (float*)g_X2;
    const int N = ACT_DIM;

    __shared__ float As[2][32][68];   // [buf][row][k]  (68 mod 32 == 4: conflict-free frags)
    __shared__ float Bs[2][64][72];   // [buf][k][n]    (72 mod 32 == 8: conflict-free frags)

    int tid   = threadIdx.x;
    int warp  = tid >> 5;
    int lane  = tid & 31;
    int group = lane >> 2;            // 0..7
    int tig   = lane & 3;             // 0..3

    int brow   = blockIdx.y * 32;
    int bcol   = blockIdx.x * 64;
    int warp_m = (warp >> 2) * 16;
    int warp_n = (warp & 3)  * 16;

    // A-load geometry: 2 float4 per thread per tile (32x64 tile)
    int ar = tid >> 3;                // 0..31
    int ac = tid & 7;                 // 0..7 (float4 idx within 32-wide half)
    int arow = brow + ar;
    int ce = 0, rr = 0;
    const float* Ah = nullptr;
    if (FIRST) { ce = cur[arow]; rr = qr[arow]; }
    else       { Ah = (const float*)g_H; }

    auto loadA = [&](int k0, int half) -> float4 {
        int kk = k0 + half * 32 + ac * 4;
        if (FIRST) {
            if (kk < ENT_D)
                return *reinterpret_cast<const float4*>(ent_emb + (size_t)ce * ENT_D + kk);
            if (kk < ENT_D + HIST_D)
                return *reinterpret_cast<const float4*>(hist + (size_t)arow * HIST_D + (kk - ENT_D));
            return *reinterpret_cast<const float4*>(rel_emb + (size_t)rr * REL_D + (kk - ENT_D - HIST_D));
        } else {
            return *reinterpret_cast<const float4*>(Ah + (size_t)arow * ACT_DIM + kk);
        }
    };

    // B-load geometry: 4 float4 per thread per tile (64x64 tile)
    int bk0 = tid >> 4;               // 0..15
    int bc0 = tid & 15;
    auto loadB = [&](int k0, int it) -> float4 {
        int kk = bk0 + it * 16;
        return *reinterpret_cast<const float4*>(&W[(size_t)(k0 + kk) * N + bcol + bc0 * 4]);
    };
    auto storeTile = [&](int buf, float4 a0, float4 a1,
                         float4 b0, float4 b1, float4 b2, float4 b3) {
        As[buf][ar][ac * 4 + 0]      = to_tf32(a0.x);
        As[buf][ar][ac * 4 + 1]      = to_tf32(a0.y);
        As[buf][ar][ac * 4 + 2]      = to_tf32(a0.z);
        As[buf][ar][ac * 4 + 3]      = to_tf32(a0.w);
        As[buf][ar][32 + ac * 4 + 0] = to_tf32(a1.x);
        As[buf][ar][32 + ac * 4 + 1] = to_tf32(a1.y);
        As[buf][ar][32 + ac * 4 + 2] = to_tf32(a1.z);
        As[buf][ar][32 + ac * 4 + 3] = to_tf32(a1.w);
        float4 bv[4] = {b0, b1, b2, b3};
#pragma unroll
        for (int i = 0; i < 4; i++) {
            Bs[buf][bk0 + i * 16][bc0 * 4 + 0] = to_tf32(bv[i].x);
            Bs[buf][bk0 + i * 16][bc0 * 4 + 1] = to_tf32(bv[i].y);
            Bs[buf][bk0 + i * 16][bc0 * 4 + 2] = to_tf32(bv[i].z);
            Bs[buf][bk0 + i * 16][bc0 * 4 + 3] = to_tf32(bv[i].w);
        }
    };

    float c[2][4];
#pragma unroll
    for (int j = 0; j < 2; j++)
#pragma unroll
        for (int i = 0; i < 4; i++) c[j][i] = 0.f;

    // prologue: tile 0
    storeTile(0, loadA(0, 0), loadA(0, 1),
                 loadB(0, 0), loadB(0, 1), loadB(0, 2), loadB(0, 3));
    __syncthreads();

    const int NIT = K / 64;
    for (int it = 0; it < NIT; it++) {
        int cb = it & 1, nb = cb ^ 1;
        float4 a0, a1, b0, b1, b2, b3;
        bool more = (it + 1 < NIT);
        if (more) {                       // issue next-tile LDGs early
            int k0 = (it + 1) * 64;
            a0 = loadA(k0, 0); a1 = loadA(k0, 1);
            b0 = loadB(k0, 0); b1 = loadB(k0, 1);
            b2 = loadB(k0, 2); b3 = loadB(k0, 3);
        }

#pragma unroll
        for (int ks = 0; ks < 8; ks++) {
            int kb = ks * 8;
            uint32_t ra0 = __float_as_uint(As[cb][warp_m + group    ][kb + tig    ]);
            uint32_t ra1 = __float_as_uint(As[cb][warp_m + group + 8][kb + tig    ]);
            uint32_t ra2 = __float_as_uint(As[cb][warp_m + group    ][kb + tig + 4]);
            uint32_t ra3 = __float_as_uint(As[cb][warp_m + group + 8][kb + tig + 4]);
#pragma unroll
            for (int j = 0; j < 2; j++) {
                int col = warp_n + j * 8 + group;
                uint32_t rb0 = __float_as_uint(Bs[cb][kb + tig    ][col]);
                uint32_t rb1 = __float_as_uint(Bs[cb][kb + tig + 4][col]);
                asm volatile(
                    "mma.sync.aligned.m16n8k8.row.col.f32.tf32.tf32.f32 "
                    "{%0,%1,%2,%3}, {%4,%5,%6,%7}, {%8,%9}, {%0,%1,%2,%3};"
                    : "+f"(c[j][0]), "+f"(c[j][1]), "+f"(c[j][2]), "+f"(c[j][3])
                    : "r"(ra0), "r"(ra1), "r"(ra2), "r"(ra3), "r"(rb0), "r"(rb1));
            }
        }

        if (more) storeTile(nb, a0, a1, b0, b1, b2, b3);
        __syncthreads();
    }

    // epilogue
#pragma unroll
    for (int j = 0; j < 2; j++) {
        int row = brow + warp_m + group;
        int col = bcol + warp_n + j * 8 + 2 * tig;
        float bc0 = bias[col], bc1 = bias[col + 1];
        float v00 = c[j][0] + bc0, v01 = c[j][1] + bc1;
        float v10 = c[j][2] + bc0, v11 = c[j][3] + bc1;
        if (FIRST) {
            v00 = fmaxf(v00, 0.f); v01 = fmaxf(v01, 0.f);
            v10 = fmaxf(v10, 0.f); v11 = fmaxf(v11, 0.f);
        }
        C[(size_t)row * N + col]           = v00;
        C[(size_t)row * N + col + 1]       = v01;
        C[(size_t)(row + 8) * N + col]     = v10;
        C[(size_t)(row + 8) * N + col + 1] = v11;
    }
}

// ---------------------------------------------------------------------------
// Fused scores + softmax + entropy. One block per batch row, 512 threads.
// 8 threads/action, 64 action-slots, 4 passes. Ent float4s batched (MLP=8);
// rel part streamed (L2-resident table). Softmax/entropy in-block.
// out: [0..B*A) action_dist, [B*A..B*A+B) entropy.
// ---------------------------------------------------------------------------
__global__ void __launch_bounds__(512, 2)
scores_softmax_kernel(const int* __restrict__ r_space,
                      const int* __restrict__ e_space,
                      const int* __restrict__ amask,
                      const float* __restrict__ rel_emb,
                      const float* __restrict__ ent_emb,
                      float* __restrict__ out) {
    int b    = blockIdx.x;
    int tid  = threadIdx.x;          // 0..511
    int lane = tid & 31;
    int warp = tid >> 5;             // 0..15
    int sub  = tid & 7;              // lane within action group
    int slot = tid >> 3;             // 0..63

    __shared__ float x2s[ACT_DIM];
    __shared__ float sc[NACT];
    __shared__ float red[16];

    x2s[tid] = g_X2[(size_t)b * ACT_DIM + tid];
    __syncthreads();

    const float4* xa = reinterpret_cast<const float4*>(x2s);

#pragma unroll
    for (int pass = 0; pass < 4; pass++) {
        int a = slot + pass * 64;
        int r = r_space[b * NACT + a];
        int e = e_space[b * NACT + a];
        const float4* rp4 = reinterpret_cast<const float4*>(rel_emb + (size_t)r * REL_D);
        const float4* ep4 = reinterpret_cast<const float4*>(ent_emb + (size_t)e * ENT_D);

        // batch ent gathers (DRAM-bound) as 8 independent loads
        float4 ev[8];
#pragma unroll
        for (int i = 0; i < 8; i++) ev[i] = ep4[sub + i * 8];

        // rel part streamed (L2-hit) while ent loads in flight
        float s = 0.f;
#pragma unroll
        for (int i = 0; i < 8; i++) {
            float4 rv = rp4[sub + i * 8];
            float4 xv = xa[sub + i * 8];
            s += rv.x * xv.x + rv.y * xv.y + rv.z * xv.z + rv.w * xv.w;
        }
#pragma unroll
        for (int i = 0; i < 8; i++) {
            float4 xw = xa[64 + sub + i * 8];
            s += ev[i].x * xw.x + ev[i].y * xw.y + ev[i].z * xw.z + ev[i].w * xw.w;
        }

        s += __shfl_xor_sync(0xffffffffu, s, 1);
        s += __shfl_xor_sync(0xffffffffu, s, 2);
        s += __shfl_xor_sync(0xffffffffu, s, 4);

        if (sub == 0) {
            float m = (float)amask[b * NACT + a];
            sc[a] = s - (1.0f - m) * HUGE_F;
        }
    }
    __syncthreads();

    // softmax over sc[0..255]; threads >=256 carry a -HUGE dummy (exp -> 0)
    float v = (tid < NACT) ? sc[tid] : -HUGE_F;

    float m = v;
#pragma unroll
    for (int o = 16; o; o >>= 1) m = fmaxf(m, __shfl_xor_sync(0xffffffffu, m, o));
    if (lane == 0) red[warp] = m;
    __syncthreads();
    float mx = red[0];
#pragma unroll
    for (int i = 1; i < 16; i++) mx = fmaxf(mx, red[i]);
    __syncthreads();

    float ev = __expf(v - mx);
    float s = ev;
#pragma unroll
    for (int o = 16; o; o >>= 1) s += __shfl_xor_sync(0xffffffffu, s, o);
    if (lane == 0) red[warp] = s;
    __syncthreads();
    float tot = red[0];
#pragma unroll
    for (int i = 1; i < 16; i++) tot += red[i];
    __syncthreads();

    float p = ev / tot;
    if (tid < NACT) out[(size_t)b * NACT + tid] = p;

    float et = -p * __logf(p + EPS_F);
#pragma unroll
    for (int o = 16; o; o >>= 1) et += __shfl_xor_sync(0xffffffffu, et, o);
    if (lane == 0) red[warp] = et;
    __syncthreads();
    if (tid == 0) {
        float e = red[0];
#pragma unroll
        for (int i = 1; i < 16; i++) e += red[i];
        out[(size_t)BATCH * NACT + b] = e;
    }
}

// ---------------------------------------------------------------------------
extern "C" void kernel_launch(void* const* d_in, const int* in_sizes, int n_in,
                              void* d_out, int out_size) {
    const int*   cur     = (const int*)  d_in[0];
    const int*   qr      = (const int*)  d_in[1];
    const float* hist    = (const float*)d_in[2];
    const int*   r_space = (const int*)  d_in[3];
    const int*   e_space = (const int*)  d_in[4];
    const int*   amask   = (const int*)  d_in[5];
    const float* ent_emb = (const float*)d_in[6];
    const float* rel_emb = (const float*)d_in[7];
    const float* W1      = (const float*)d_in[8];
    const float* b1      = (const float*)d_in[9];
    const float* W2      = (const float*)d_in[10];
    const float* b2      = (const float*)d_in[11];
    float* out = (float*)d_out;

    dim3 ggrid(ACT_DIM / 64, BATCH / 32);    // 8 x 16 = 128 blocks
    mma_gemm_kernel<IN_DIM,  true ><<<ggrid, 256>>>(W1, b1, cur, qr, hist, ent_emb, rel_emb);
    mma_gemm_kernel<ACT_DIM, false><<<ggrid, 256>>>(W2, b2, cur, qr, hist, ent_emb, rel_emb);

    scores_softmax_kernel<<<BATCH, 512>>>(r_space, e_space, amask,
                                          rel_emb, ent_emb, out);
}